// round 4
// baseline (speedup 1.0000x reference)
#include <cuda_runtime.h>
#include <cuda_bf16.h>
#include <math.h>
#include <stdint.h>

#define BB 32
#define NN 2048
#define DD 256

#define L2_LAMDA 0.001f
#define RECONS_LAMDA 0.2f
#define LB_TH 0.01f

// ---------------------------------------------------------------------------
// Device scratch
// ---------------------------------------------------------------------------
__device__ __nv_bfloat16 g_cur_bf[(size_t)BB * NN * DD];   // [b][n][k]
__device__ __nv_bfloat16 g_pre_bf[(size_t)BB * NN * DD];   // [b][m][d]  (natural)
__device__ __nv_bfloat16 g_w_bf[(size_t)NN * NN];          // NEGATED masked incidence [n][m]
__device__ __nv_bfloat16 g_r_bf[DD * DD];                  // [k][j]     (natural)
__device__ float g_rowterm[NN];
__device__ float g_part[2 * BB * NN];                      // [dtile][b][n]

// ---------------------------------------------------------------------------
// PTX helpers
// ---------------------------------------------------------------------------
__device__ __forceinline__ uint32_t smem_u32(const void* p) {
    uint32_t a;
    asm("{ .reg .u64 t; cvta.to.shared.u64 t, %1; cvt.u32.u64 %0, t; }"
        : "=r"(a) : "l"(p));
    return a;
}

__device__ __forceinline__ void cp16(uint32_t dst, const void* src) {
    asm volatile("cp.async.cg.shared.global [%0], [%1], 16;"
                 :: "r"(dst), "l"(src) : "memory");
}
#define CP_COMMIT() asm volatile("cp.async.commit_group;" ::: "memory")

__device__ __forceinline__ void ldsm_x4(uint32_t& r0, uint32_t& r1,
                                        uint32_t& r2, uint32_t& r3, uint32_t addr) {
    asm volatile("ldmatrix.sync.aligned.m8n8.x4.shared.b16 {%0,%1,%2,%3}, [%4];"
                 : "=r"(r0), "=r"(r1), "=r"(r2), "=r"(r3) : "r"(addr));
}
__device__ __forceinline__ void ldsm_x4t(uint32_t& r0, uint32_t& r1,
                                         uint32_t& r2, uint32_t& r3, uint32_t addr) {
    asm volatile("ldmatrix.sync.aligned.m8n8.x4.trans.shared.b16 {%0,%1,%2,%3}, [%4];"
                 : "=r"(r0), "=r"(r1), "=r"(r2), "=r"(r3) : "r"(addr));
}

__device__ __forceinline__ void mma16816(float* d, const uint32_t* a, const uint32_t* b) {
    asm volatile(
        "mma.sync.aligned.m16n8k16.row.col.f32.bf16.bf16.f32 "
        "{%0,%1,%2,%3}, {%4,%5,%6,%7}, {%8,%9}, {%0,%1,%2,%3};"
        : "+f"(d[0]), "+f"(d[1]), "+f"(d[2]), "+f"(d[3])
        : "r"(a[0]), "r"(a[1]), "r"(a[2]), "r"(a[3]), "r"(b[0]), "r"(b[1]));
}

// SW128 swizzle for 128B rows
#define SWZ(o) ((uint32_t)(o) ^ ((((uint32_t)(o)) >> 3) & 0x70))

// ---------------------------------------------------------------------------
// Straight fp32 -> bf16 conversion. which: 0=cur, 1=pre, 2=R
// ---------------------------------------------------------------------------
__global__ __launch_bounds__(256) void conv_kernel(const float4* __restrict__ src,
                                                   int which, int n4) {
    int i = blockIdx.x * blockDim.x + threadIdx.x;
    if (i >= n4) return;
    __nv_bfloat162* dst = (which == 0) ? (__nv_bfloat162*)g_cur_bf
                        : (which == 1) ? (__nv_bfloat162*)g_pre_bf
                                       : (__nv_bfloat162*)g_r_bf;
    float4 v = src[i];
    dst[2 * i]     = __floats2bfloat162_rn(v.x, v.y);
    dst[2 * i + 1] = __floats2bfloat162_rn(v.z, v.w);
}

// Masked+negated bf16 incidence + per-row l1/l2 stats
__global__ __launch_bounds__(256) void conv_inc_kernel(const float* __restrict__ inc) {
    int n = blockIdx.x;
    int tid = threadIdx.x;
    const float4* row = (const float4*)(inc + (size_t)n * NN);
    __nv_bfloat162* wrow = (__nv_bfloat162*)(g_w_bf + (size_t)n * NN);

    float mx = 0.0f, sq = 0.0f;
    for (int i = tid; i < NN / 4; i += 256) {
        float4 v = row[i];
        float a = (v.x > LB_TH) ? v.x : 0.0f;
        float b = (v.y > LB_TH) ? v.y : 0.0f;
        float c = (v.z > LB_TH) ? v.z : 0.0f;
        float d = (v.w > LB_TH) ? v.w : 0.0f;
        mx = fmaxf(mx, fmaxf(fmaxf(a, b), fmaxf(c, d)));
        sq += a * a + b * b + c * c + d * d;
        wrow[2 * i]     = __floats2bfloat162_rn(-a, -b);
        wrow[2 * i + 1] = __floats2bfloat162_rn(-c, -d);
    }

    __shared__ float smx[256];
    __shared__ float ssq[256];
    smx[tid] = mx; ssq[tid] = sq;
    __syncthreads();
    for (int s = 128; s > 0; s >>= 1) {
        if (tid < s) {
            smx[tid] = fmaxf(smx[tid], smx[tid + s]);
            ssq[tid] += ssq[tid + s];
        }
        __syncthreads();
    }
    if (tid == 0) g_rowterm[n] = smx[0] + L2_LAMDA * sqrtf(ssq[0]);
}

// ---------------------------------------------------------------------------
// Main GEMM. CTA = (dtile 0..1, ntile 0..15, bpair 0..15), handles batches
// b0 = 2*bpair, b1 = b0+1 for one 128(n) x 128(d) tile:
//   diff[g] = cur[bg] @ R + (-W) @ pre[bg]
// Phase A (4 chunks, K=256): B operand (R) shared between g.
// Phase B (32 chunks, K=2048): A operand (W) shared between g.
// SMEM per stage (48KB): S (shared op 16KB) | P0 (16KB) | P1 (16KB).
//   K-major tiles (A-type):   128 rows x 64 k,  128B rows, SW128 swizzle.
//   Trans tiles (B-type):     64 rows(k) x 128 j, 256B rows, chunk^=(row&7).
// 8 warps: warp_m = w&3 (32 rows), warp_n = w>>2 (64 cols).
// ---------------------------------------------------------------------------
#define CHUNKS 36
#define STAGE_BYTES 49152
#define NSTAGE 3
#define GEMM_SMEM (NSTAGE * STAGE_BYTES)   // 147456

__global__ __launch_bounds__(256, 1) void gemm_kernel() {
    extern __shared__ char smem[];
    const uint32_t sb = smem_u32(smem);
    const int tid = threadIdx.x;
    const int lane = tid & 31;
    const int w = tid >> 5;
    const int warp_m = w & 3;
    const int warp_n = w >> 2;

    const int dtile = blockIdx.x;
    const int ntile = blockIdx.y;
    const int b0    = blockIdx.z * 2;
    const int n0 = ntile * 128;
    const int d0 = dtile * 128;

    float acc[2][2][8][4];
#pragma unroll
    for (int g = 0; g < 2; g++)
#pragma unroll
        for (int mt = 0; mt < 2; mt++)
#pragma unroll
            for (int nt = 0; nt < 8; nt++)
#pragma unroll
                for (int i = 0; i < 4; i++) acc[g][mt][nt][i] = 0.0f;

    // ---- per-lane ldmatrix address precompute ----
    // A (K-major, 128B rows): rows warp_m*32 + mt*16 + (lane&15); row&7 == lane&7
    uint32_t arow[2];
#pragma unroll
    for (int mt = 0; mt < 2; mt++)
        arow[mt] = (uint32_t)(warp_m * 32 + mt * 16 + (lane & 15)) * 128;
    const uint32_t alx = (lane & 7);
    const uint32_t ahi = (lane >> 4);   // chunk high bit from lane
    // B (trans, 256B rows): krow = lane&15, column-half = lane>>4
    // chunk cb = warp_n*8 + jg*2 + (lane>>4), swizzled ^ (krow&7) = ^(lane&7)
    uint32_t btb[4];
#pragma unroll
    for (int jg = 0; jg < 4; jg++) {
        uint32_t cb = (uint32_t)(warp_n * 8 + jg * 2) + (lane >> 4);
        btb[jg] = (uint32_t)(lane & 15) * 256 + ((cb ^ (lane & 7)) << 4);
    }

    const __nv_bfloat16* curb0 = g_cur_bf + ((size_t)b0 * NN + n0) * DD;
    const __nv_bfloat16* curb1 = curb0 + (size_t)NN * DD;
    const __nv_bfloat16* preb0 = g_pre_bf + (size_t)b0 * NN * DD + d0;
    const __nv_bfloat16* preb1 = preb0 + (size_t)NN * DD;
    const __nv_bfloat16* wb    = g_w_bf + (size_t)n0 * NN;
    const __nv_bfloat16* rb    = g_r_bf + d0;

    // ---- load helpers (1024 cp16 each = 4 per thread) ----
#define LOAD_KM(dst, src, ld)                                                  \
    _Pragma("unroll")                                                          \
    for (int i = 0; i < 4; i++) {                                              \
        int o = tid + i * 256;                                                 \
        int row = o >> 3, seg = o & 7;                                         \
        cp16((dst) + SWZ(row * 128 + seg * 16), (src) + (size_t)row * (ld) + seg * 8); \
    }
#define LOAD_TR(dst, src, ld)                                                  \
    _Pragma("unroll")                                                          \
    for (int i = 0; i < 4; i++) {                                              \
        int o = tid + i * 256;                                                 \
        int row = o >> 4, seg = o & 15;                                        \
        cp16((dst) + row * 256 + (((seg ^ (row & 7))) << 4),                   \
             (src) + (size_t)row * (ld) + seg * 8);                            \
    }

#define LOAD_CHUNK(c)                                                          \
    {                                                                          \
        const uint32_t st = sb + ((c) % NSTAGE) * STAGE_BYTES;                 \
        if ((c) < 4) {                                                         \
            int k0 = (c) * 64;                                                 \
            LOAD_TR(st, rb + (size_t)k0 * DD, DD);                             \
            LOAD_KM(st + 16384, curb0 + k0, DD);                               \
            LOAD_KM(st + 32768, curb1 + k0, DD);                               \
        } else {                                                               \
            int k0 = ((c) - 4) * 64;                                           \
            LOAD_KM(st, wb + k0, NN);                                          \
            LOAD_TR(st + 16384, preb0 + (size_t)k0 * DD, DD);                  \
            LOAD_TR(st + 32768, preb1 + (size_t)k0 * DD, DD);                  \
        }                                                                      \
        CP_COMMIT();                                                           \
    }

    LOAD_CHUNK(0);
    LOAD_CHUNK(1);
    LOAD_CHUNK(2);

    for (int c = 0; c < CHUNKS; c++) {
        // wait for stage c (2 newer groups may remain pending)
        if (c + 3 < CHUNKS)
            asm volatile("cp.async.wait_group 2;" ::: "memory");
        else if (c + 2 < CHUNKS)
            asm volatile("cp.async.wait_group 1;" ::: "memory");
        else
            asm volatile("cp.async.wait_group 0;" ::: "memory");
        __syncthreads();

        const uint32_t sS = sb + (c % NSTAGE) * STAGE_BYTES;
        const uint32_t sP0 = sS + 16384;
        const uint32_t sP1 = sS + 32768;

        if (c < 4) {
            // B (R) shared, A (cur) per batch
#pragma unroll
            for (int s = 0; s < 4; s++) {
                uint32_t bf[8][2];
#pragma unroll
                for (int jg = 0; jg < 4; jg++)
                    ldsm_x4t(bf[2 * jg][0], bf[2 * jg][1],
                             bf[2 * jg + 1][0], bf[2 * jg + 1][1],
                             sS + s * 4096 + btb[jg]);
#pragma unroll
                for (int g = 0; g < 2; g++) {
                    const uint32_t sP = g ? sP1 : sP0;
                    uint32_t a[2][4];
#pragma unroll
                    for (int mt = 0; mt < 2; mt++) {
                        uint32_t ch = (uint32_t)(s * 2) + ahi;
                        ldsm_x4(a[mt][0], a[mt][1], a[mt][2], a[mt][3],
                                sP + arow[mt] + ((ch ^ alx) << 4));
                    }
#pragma unroll
                    for (int mt = 0; mt < 2; mt++)
#pragma unroll
                        for (int nt = 0; nt < 8; nt++)
                            mma16816(acc[g][mt][nt], a[mt], bf[nt]);
                }
            }
        } else {
            // A (W) shared, B (pre) per batch
#pragma unroll
            for (int s = 0; s < 4; s++) {
                uint32_t a[2][4];
#pragma unroll
                for (int mt = 0; mt < 2; mt++) {
                    uint32_t ch = (uint32_t)(s * 2) + ahi;
                    ldsm_x4(a[mt][0], a[mt][1], a[mt][2], a[mt][3],
                            sS + arow[mt] + ((ch ^ alx) << 4));
                }
#pragma unroll
                for (int g = 0; g < 2; g++) {
                    const uint32_t sP = g ? sP1 : sP0;
                    uint32_t bf[8][2];
#pragma unroll
                    for (int jg = 0; jg < 4; jg++)
                        ldsm_x4t(bf[2 * jg][0], bf[2 * jg][1],
                                 bf[2 * jg + 1][0], bf[2 * jg + 1][1],
                                 sP + s * 4096 + btb[jg]);
#pragma unroll
                    for (int mt = 0; mt < 2; mt++)
#pragma unroll
                        for (int nt = 0; nt < 8; nt++)
                            mma16816(acc[g][mt][nt], a[mt], bf[nt]);
                }
            }
        }
        __syncthreads();
        if (c + 3 < CHUNKS) LOAD_CHUNK(c + 3);
    }

    // ------------- epilogue: per-row sum of squares per batch -------------
    float (*red)[2] = (float(*)[2])smem;
#pragma unroll
    for (int g = 0; g < 2; g++) {
#pragma unroll
        for (int mt = 0; mt < 2; mt++) {
            float s0 = 0.0f, s1 = 0.0f;
#pragma unroll
            for (int nt = 0; nt < 8; nt++) {
                s0 = fmaf(acc[g][mt][nt][0], acc[g][mt][nt][0], s0);
                s0 = fmaf(acc[g][mt][nt][1], acc[g][mt][nt][1], s0);
                s1 = fmaf(acc[g][mt][nt][2], acc[g][mt][nt][2], s1);
                s1 = fmaf(acc[g][mt][nt][3], acc[g][mt][nt][3], s1);
            }
            s0 += __shfl_xor_sync(0xFFFFFFFF, s0, 1);
            s0 += __shfl_xor_sync(0xFFFFFFFF, s0, 2);
            s1 += __shfl_xor_sync(0xFFFFFFFF, s1, 1);
            s1 += __shfl_xor_sync(0xFFFFFFFF, s1, 2);
            if ((lane & 3) == 0) {
                int r = warp_m * 32 + mt * 16 + (lane >> 2);
                red[r][warp_n] = s0;
                red[r + 8][warp_n] = s1;
            }
        }
        __syncthreads();
        if (tid < 128) {
            float t = red[tid][0] + red[tid][1];
            g_part[((size_t)dtile * BB + (b0 + g)) * NN + n0 + tid] = t;
        }
        __syncthreads();
    }
}

// ---------------------------------------------------------------------------
// Finalize: out[b] = 0.2 * sum_n sqrt(part0 + part1) + sum_n rowterm
// ---------------------------------------------------------------------------
__global__ __launch_bounds__(256) void finalize_kernel(float* __restrict__ out) {
    int b = blockIdx.x;
    int tid = threadIdx.x;
    float srec = 0.0f, srow = 0.0f;
    for (int n = tid; n < NN; n += 256) {
        float t = g_part[((size_t)0 * BB + b) * NN + n]
                + g_part[((size_t)1 * BB + b) * NN + n];
        srec += sqrtf(t);
        srow += g_rowterm[n];
    }
    __shared__ float s1[256];
    __shared__ float s2[256];
    s1[tid] = srec; s2[tid] = srow;
    __syncthreads();
    for (int s = 128; s > 0; s >>= 1) {
        if (tid < s) { s1[tid] += s1[tid + s]; s2[tid] += s2[tid + s]; }
        __syncthreads();
    }
    if (tid == 0) out[b] = RECONS_LAMDA * s1[0] + s2[0];
}

// ---------------------------------------------------------------------------
extern "C" void kernel_launch(void* const* d_in, const int* in_sizes, int n_in,
                              void* d_out, int out_size) {
    const float* cur = nullptr;
    const float* pre = nullptr;
    const float* rproj = nullptr;
    const float* inc = nullptr;
    int big_seen = 0;
    for (int i = 0; i < n_in; i++) {
        if (in_sizes[i] == DD * DD) rproj = (const float*)d_in[i];
        else if (in_sizes[i] == NN * NN) inc = (const float*)d_in[i];
        else if (in_sizes[i] == BB * NN * DD) {
            if (big_seen == 0) cur = (const float*)d_in[i];
            else pre = (const float*)d_in[i];
            big_seen++;
        }
    }
    float* out = (float*)d_out;

    cudaFuncSetAttribute(gemm_kernel, cudaFuncAttributeMaxDynamicSharedMemorySize, GEMM_SMEM);

    const int n4_big = BB * NN * DD / 4;
    conv_kernel<<<n4_big / 256, 256>>>((const float4*)cur, 0, n4_big);
    conv_kernel<<<n4_big / 256, 256>>>((const float4*)pre, 1, n4_big);
    conv_kernel<<<DD * DD / 4 / 256, 256>>>((const float4*)rproj, 2, DD * DD / 4);
    conv_inc_kernel<<<NN, 256>>>(inc);

    gemm_kernel<<<dim3(2, 16, 16), 256, GEMM_SMEM>>>();
    finalize_kernel<<<BB, 256>>>(out);

    if (out_size >= BB + NN * NN) {
        cudaMemcpyAsync(out + BB, inc, (size_t)NN * NN * sizeof(float),
                        cudaMemcpyDeviceToDevice, 0);
    }
}

// round 5
// speedup vs baseline: 1.1387x; 1.1387x over previous
#include <cuda_runtime.h>
#include <cuda_bf16.h>
#include <math.h>
#include <stdint.h>

#define BB 32
#define NN 2048
#define DD 256

#define L2_LAMDA 0.001f
#define RECONS_LAMDA 0.2f
#define LB_TH 0.01f

// ---------------------------------------------------------------------------
// Device scratch
// ---------------------------------------------------------------------------
__device__ __nv_bfloat16 g_cur_bf[(size_t)BB * NN * DD];   // [b][n][k]
__device__ __nv_bfloat16 g_pre_bf[(size_t)BB * NN * DD];   // [b][m][d]  (natural)
__device__ __nv_bfloat16 g_w_bf[(size_t)NN * NN];          // NEGATED masked incidence [n][m]
__device__ __nv_bfloat16 g_r_bf[DD * DD];                  // [k][j]     (natural)
__device__ float g_rowterm[NN];
__device__ float g_part[2 * BB * NN];                      // [dtile][b][n]

// ---------------------------------------------------------------------------
// PTX helpers
// ---------------------------------------------------------------------------
__device__ __forceinline__ uint32_t smem_u32(const void* p) {
    uint32_t a;
    asm("{ .reg .u64 t; cvta.to.shared.u64 t, %1; cvt.u32.u64 %0, t; }"
        : "=r"(a) : "l"(p));
    return a;
}

__device__ __forceinline__ void cp16(uint32_t dst, const void* src) {
    asm volatile("cp.async.cg.shared.global [%0], [%1], 16;"
                 :: "r"(dst), "l"(src) : "memory");
}
#define CP_COMMIT() asm volatile("cp.async.commit_group;" ::: "memory")

__device__ __forceinline__ void ldsm_x4(uint32_t& r0, uint32_t& r1,
                                        uint32_t& r2, uint32_t& r3, uint32_t addr) {
    asm volatile("ldmatrix.sync.aligned.m8n8.x4.shared.b16 {%0,%1,%2,%3}, [%4];"
                 : "=r"(r0), "=r"(r1), "=r"(r2), "=r"(r3) : "r"(addr));
}
__device__ __forceinline__ void ldsm_x4t(uint32_t& r0, uint32_t& r1,
                                         uint32_t& r2, uint32_t& r3, uint32_t addr) {
    asm volatile("ldmatrix.sync.aligned.m8n8.x4.trans.shared.b16 {%0,%1,%2,%3}, [%4];"
                 : "=r"(r0), "=r"(r1), "=r"(r2), "=r"(r3) : "r"(addr));
}

__device__ __forceinline__ void mma16816(float* d, const uint32_t* a, const uint32_t* b) {
    asm volatile(
        "mma.sync.aligned.m16n8k16.row.col.f32.bf16.bf16.f32 "
        "{%0,%1,%2,%3}, {%4,%5,%6,%7}, {%8,%9}, {%0,%1,%2,%3};"
        : "+f"(d[0]), "+f"(d[1]), "+f"(d[2]), "+f"(d[3])
        : "r"(a[0]), "r"(a[1]), "r"(a[2]), "r"(a[3]), "r"(b[0]), "r"(b[1]));
}

// SW128 swizzle for 128B rows
#define SWZ(o) ((uint32_t)(o) ^ ((((uint32_t)(o)) >> 3) & 0x70))

// ---------------------------------------------------------------------------
// Straight fp32 -> bf16 conversion. which: 0=cur, 1=pre, 2=R
// ---------------------------------------------------------------------------
__global__ __launch_bounds__(256) void conv_kernel(const float4* __restrict__ src,
                                                   int which, int n4) {
    int i = blockIdx.x * blockDim.x + threadIdx.x;
    if (i >= n4) return;
    __nv_bfloat162* dst = (which == 0) ? (__nv_bfloat162*)g_cur_bf
                        : (which == 1) ? (__nv_bfloat162*)g_pre_bf
                                       : (__nv_bfloat162*)g_r_bf;
    float4 v = src[i];
    dst[2 * i]     = __floats2bfloat162_rn(v.x, v.y);
    dst[2 * i + 1] = __floats2bfloat162_rn(v.z, v.w);
}

// Masked+negated bf16 incidence + per-row l1/l2 stats
__global__ __launch_bounds__(256) void conv_inc_kernel(const float* __restrict__ inc) {
    int n = blockIdx.x;
    int tid = threadIdx.x;
    const float4* row = (const float4*)(inc + (size_t)n * NN);
    __nv_bfloat162* wrow = (__nv_bfloat162*)(g_w_bf + (size_t)n * NN);

    float mx = 0.0f, sq = 0.0f;
    for (int i = tid; i < NN / 4; i += 256) {
        float4 v = row[i];
        float a = (v.x > LB_TH) ? v.x : 0.0f;
        float b = (v.y > LB_TH) ? v.y : 0.0f;
        float c = (v.z > LB_TH) ? v.z : 0.0f;
        float d = (v.w > LB_TH) ? v.w : 0.0f;
        mx = fmaxf(mx, fmaxf(fmaxf(a, b), fmaxf(c, d)));
        sq += a * a + b * b + c * c + d * d;
        wrow[2 * i]     = __floats2bfloat162_rn(-a, -b);
        wrow[2 * i + 1] = __floats2bfloat162_rn(-c, -d);
    }

    __shared__ float smx[256];
    __shared__ float ssq[256];
    smx[tid] = mx; ssq[tid] = sq;
    __syncthreads();
    for (int s = 128; s > 0; s >>= 1) {
        if (tid < s) {
            smx[tid] = fmaxf(smx[tid], smx[tid + s]);
            ssq[tid] += ssq[tid + s];
        }
        __syncthreads();
    }
    if (tid == 0) g_rowterm[n] = smx[0] + L2_LAMDA * sqrtf(ssq[0]);
}

// ---------------------------------------------------------------------------
// Main GEMM: per CTA (dtile, ntile, b) compute 128x128 tile of
//   diff = cur_b @ R + (-W) @ pre_b   (fp32 reg accum, bf16 HMMA)
// then per-row sum of squares -> g_part.
// A smem: [128 rows][64 k] K-major, 128B rows, SW128.
// B smem: [64 k][128 j] trans layout, 256B rows, chunk ^= (krow & 7).
// 3-stage cp.async pipeline, ONE __syncthreads per chunk.
// 8 warps: warp_m = w&3 (32 rows), warp_n = w>>2 (64 cols).
// ---------------------------------------------------------------------------
#define CHUNKS 36            // 4 (cur@R, K=256) + 32 (W@pre, K=2048)
#define STAGE_BYTES 32768    // 16KB A + 16KB B
#define NSTAGE 3
#define GEMM_SMEM (NSTAGE * STAGE_BYTES)   // 98304; x2 CTAs = 192KB

__global__ __launch_bounds__(256, 2) void gemm_kernel() {
    extern __shared__ char smem[];
    const uint32_t sb = smem_u32(smem);
    const int tid = threadIdx.x;
    const int lane = tid & 31;
    const int w = tid >> 5;
    const int warp_m = w & 3;
    const int warp_n = w >> 2;

    const int dtile = blockIdx.x;           // 0..1
    const int ntile = blockIdx.y;           // 0..15
    const int b     = blockIdx.z;           // 0..31
    const int n0 = ntile * 128;
    const int d0 = dtile * 128;

    float acc[2][8][4];
#pragma unroll
    for (int mt = 0; mt < 2; mt++)
#pragma unroll
        for (int nt = 0; nt < 8; nt++)
#pragma unroll
            for (int i = 0; i < 4; i++) acc[mt][nt][i] = 0.0f;

    // ---- per-lane ldmatrix address precompute ----
    uint32_t arow[2];
#pragma unroll
    for (int mt = 0; mt < 2; mt++)
        arow[mt] = (uint32_t)(warp_m * 32 + mt * 16 + (lane & 15)) * 128;
    const uint32_t alx = (lane & 7);
    const uint32_t ahi = (lane >> 4);
    uint32_t btb[4];
#pragma unroll
    for (int jg = 0; jg < 4; jg++) {
        uint32_t cb = (uint32_t)(warp_n * 8 + jg * 2) + (lane >> 4);
        btb[jg] = (uint32_t)(lane & 15) * 256 + ((cb ^ (lane & 7)) << 4);
    }

    const __nv_bfloat16* curb = g_cur_bf + ((size_t)b * NN + n0) * DD;
    const __nv_bfloat16* preb = g_pre_bf + (size_t)b * NN * DD + d0;
    const __nv_bfloat16* wb   = g_w_bf + (size_t)n0 * NN;
    const __nv_bfloat16* rb   = g_r_bf + d0;

    // A (K-major): 128 rows x 128B; B (trans): 64 rows x 256B. 4 cp16/thread each.
#define LOAD_KM(dst, src, ld)                                                   \
    _Pragma("unroll")                                                           \
    for (int i = 0; i < 4; i++) {                                               \
        int o = tid + i * 256;                                                  \
        int row = o >> 3, seg = o & 7;                                          \
        cp16((dst) + SWZ(row * 128 + seg * 16),                                 \
             (src) + (size_t)row * (ld) + seg * 8);                             \
    }
#define LOAD_TR(dst, src, ld)                                                   \
    _Pragma("unroll")                                                           \
    for (int i = 0; i < 4; i++) {                                               \
        int o = tid + i * 256;                                                  \
        int row = o >> 4, seg = o & 15;                                         \
        cp16((dst) + row * 256 + (((seg ^ (row & 7))) << 4),                    \
             (src) + (size_t)row * (ld) + seg * 8);                             \
    }

#define LOAD_CHUNK(c)                                                           \
    {                                                                           \
        const uint32_t st = sb + ((c) % NSTAGE) * STAGE_BYTES;                  \
        if ((c) < 4) {                                                          \
            int k0 = (c) * 64;                                                  \
            LOAD_KM(st, curb + k0, DD);                                         \
            LOAD_TR(st + 16384, rb + (size_t)k0 * DD, DD);                      \
        } else {                                                                \
            int k0 = ((c) - 4) * 64;                                            \
            LOAD_KM(st, wb + k0, NN);                                           \
            LOAD_TR(st + 16384, preb + (size_t)k0 * DD, DD);                    \
        }                                                                       \
        CP_COMMIT();                                                            \
    }

    // prologue: NSTAGE-1 stages in flight
    LOAD_CHUNK(0);
    LOAD_CHUNK(1);

    for (int c = 0; c < CHUNKS; c++) {
        if (c + 1 < CHUNKS)
            asm volatile("cp.async.wait_group 1;" ::: "memory");
        else
            asm volatile("cp.async.wait_group 0;" ::: "memory");
        __syncthreads();

        // prefetch into the slot consumed LAST iteration (safe after the sync)
        if (c + 2 < CHUNKS) LOAD_CHUNK(c + 2);

        const uint32_t sA = sb + (c % NSTAGE) * STAGE_BYTES;
        const uint32_t sB = sA + 16384;

#pragma unroll
        for (int s = 0; s < 4; s++) {
            uint32_t a[2][4];
#pragma unroll
            for (int mt = 0; mt < 2; mt++) {
                uint32_t ch = (uint32_t)(s * 2) + ahi;
                ldsm_x4(a[mt][0], a[mt][1], a[mt][2], a[mt][3],
                        sA + arow[mt] + ((ch ^ alx) << 4));
            }
            uint32_t bf[8][2];
#pragma unroll
            for (int jg = 0; jg < 4; jg++)
                ldsm_x4t(bf[2 * jg][0], bf[2 * jg][1],
                         bf[2 * jg + 1][0], bf[2 * jg + 1][1],
                         sB + s * 4096 + btb[jg]);
#pragma unroll
            for (int mt = 0; mt < 2; mt++)
#pragma unroll
                for (int nt = 0; nt < 8; nt++)
                    mma16816(acc[mt][nt], a[mt], bf[nt]);
        }
    }

    // ------------- epilogue: per-row sum of squares -------------
    __shared__ float red[128][2];
#pragma unroll
    for (int mt = 0; mt < 2; mt++) {
        float s0 = 0.0f, s1 = 0.0f;
#pragma unroll
        for (int nt = 0; nt < 8; nt++) {
            s0 = fmaf(acc[mt][nt][0], acc[mt][nt][0], s0);
            s0 = fmaf(acc[mt][nt][1], acc[mt][nt][1], s0);
            s1 = fmaf(acc[mt][nt][2], acc[mt][nt][2], s1);
            s1 = fmaf(acc[mt][nt][3], acc[mt][nt][3], s1);
        }
        s0 += __shfl_xor_sync(0xFFFFFFFF, s0, 1);
        s0 += __shfl_xor_sync(0xFFFFFFFF, s0, 2);
        s1 += __shfl_xor_sync(0xFFFFFFFF, s1, 1);
        s1 += __shfl_xor_sync(0xFFFFFFFF, s1, 2);
        if ((lane & 3) == 0) {
            int r = warp_m * 32 + mt * 16 + (lane >> 2);
            red[r][warp_n] = s0;
            red[r + 8][warp_n] = s1;
        }
    }
    __syncthreads();
    if (tid < 128) {
        float t = red[tid][0] + red[tid][1];
        g_part[((size_t)dtile * BB + b) * NN + n0 + tid] = t;
    }
}

// ---------------------------------------------------------------------------
// Finalize: out[b] = 0.2 * sum_n sqrt(part0 + part1) + sum_n rowterm
// ---------------------------------------------------------------------------
__global__ __launch_bounds__(256) void finalize_kernel(float* __restrict__ out) {
    int b = blockIdx.x;
    int tid = threadIdx.x;
    float srec = 0.0f, srow = 0.0f;
    for (int n = tid; n < NN; n += 256) {
        float t = g_part[((size_t)0 * BB + b) * NN + n]
                + g_part[((size_t)1 * BB + b) * NN + n];
        srec += sqrtf(t);
        srow += g_rowterm[n];
    }
    __shared__ float s1[256];
    __shared__ float s2[256];
    s1[tid] = srec; s2[tid] = srow;
    __syncthreads();
    for (int s = 128; s > 0; s >>= 1) {
        if (tid < s) { s1[tid] += s1[tid + s]; s2[tid] += s2[tid + s]; }
        __syncthreads();
    }
    if (tid == 0) out[b] = RECONS_LAMDA * s1[0] + s2[0];
}

// ---------------------------------------------------------------------------
extern "C" void kernel_launch(void* const* d_in, const int* in_sizes, int n_in,
                              void* d_out, int out_size) {
    const float* cur = nullptr;
    const float* pre = nullptr;
    const float* rproj = nullptr;
    const float* inc = nullptr;
    int big_seen = 0;
    for (int i = 0; i < n_in; i++) {
        if (in_sizes[i] == DD * DD) rproj = (const float*)d_in[i];
        else if (in_sizes[i] == NN * NN) inc = (const float*)d_in[i];
        else if (in_sizes[i] == BB * NN * DD) {
            if (big_seen == 0) cur = (const float*)d_in[i];
            else pre = (const float*)d_in[i];
            big_seen++;
        }
    }
    float* out = (float*)d_out;

    cudaFuncSetAttribute(gemm_kernel, cudaFuncAttributeMaxDynamicSharedMemorySize, GEMM_SMEM);

    const int n4_big = BB * NN * DD / 4;
    conv_kernel<<<n4_big / 256, 256>>>((const float4*)cur, 0, n4_big);
    conv_kernel<<<n4_big / 256, 256>>>((const float4*)pre, 1, n4_big);
    conv_kernel<<<DD * DD / 4 / 256, 256>>>((const float4*)rproj, 2, DD * DD / 4);
    conv_inc_kernel<<<NN, 256>>>(inc);

    gemm_kernel<<<dim3(2, 16, BB), 256, GEMM_SMEM>>>();
    finalize_kernel<<<BB, 256>>>(out);

    if (out_size >= BB + NN * NN) {
        cudaMemcpyAsync(out + BB, inc, (size_t)NN * NN * sizeof(float),
                        cudaMemcpyDeviceToDevice, 0);
    }
}